// round 3
// baseline (speedup 1.0000x reference)
#include <cuda_runtime.h>
#include <math.h>

// Problem constants
#define B_ 2
#define CC 512      // concat channels
#define CO 256      // output channels
#define C1 512      // x1 channels
#define H_ 64
#define W_ 64
#define HW 4096
#define HWIN 1024
#define OFFC 18
#define K2 9

typedef unsigned long long ull;

// Packed f32x2 helpers (Blackwell FFMA2 path)
__device__ __forceinline__ ull pack2(float lo, float hi) {
    ull r; asm("mov.b64 %0, {%1,%2};" : "=l"(r) : "f"(lo), "f"(hi)); return r;
}
__device__ __forceinline__ void fma2(ull& d, ull a, ull b) {
    asm("fma.rn.f32x2 %0, %1, %2, %0;" : "+l"(d) : "l"(a), "l"(b));
}
__device__ __forceinline__ float2 unpack2(ull v) {
    float2 r; asm("mov.b64 {%0,%1}, %2;" : "=f"(r.x), "=f"(r.y) : "l"(v)); return r;
}

// Scratch (device globals; no runtime allocation)
__device__ float g_t[B_ * CO * HWIN];          // 1x1-conv'd x1 @ 32x32 (no bias)
__device__ __align__(16) float g_x[B_ * CC * HW];  // concat tensor [b][512][64][64]
__device__ float g_off[B_ * OFFC * HW];        // final offset field
__device__ float g_offp[B_ * 4 * OFFC * HW];   // offset partials (4 ci-chunks)
__device__ float g_dc[B_ * CO * HW];           // deform conv output (+def_b)
__device__ __align__(16) float g_wT[K2 * CC * CO + 256];  // def_w [k][ci][co] (+pad)
__device__ float g_stats[2 * CO];              // mean, rstd per channel

// ---------------------------------------------------------------------------
// 1x1 conv on x1 at 32x32 (transposed weight staging + FFMA2)
__global__ void k_upconv(const float* __restrict__ x1,
                         const float* __restrict__ up_w) {
    __shared__ __align__(16) float ws[8 * 512];   // [ci][j]
    int b = blockIdx.z;
    int co0 = blockIdx.y * 8;
    int p = blockIdx.x * 128 + threadIdx.x;
    for (int i = threadIdx.x; i < 4096; i += 128) {
        int j = i >> 9, ci = i & 511;
        ws[ci * 8 + j] = up_w[(co0 + j) * 512 + ci];
    }
    __syncthreads();
    ull a[4] = {0ull, 0ull, 0ull, 0ull};
    const float* xp = x1 + b * C1 * HWIN + p;
#pragma unroll 4
    for (int ci = 0; ci < 512; ci++) {
        float xv = __ldg(xp + ci * HWIN);
        ull xv2 = pack2(xv, xv);
        const ull* wr = (const ull*)(ws + ci * 8);
        fma2(a[0], wr[0], xv2);
        fma2(a[1], wr[1], xv2);
        fma2(a[2], wr[2], xv2);
        fma2(a[3], wr[3], xv2);
    }
#pragma unroll
    for (int jp = 0; jp < 4; jp++) {
        float2 u = unpack2(a[jp]);
        g_t[(b * CO + co0 + 2 * jp) * HWIN + p] = u.x;
        g_t[(b * CO + co0 + 2 * jp + 1) * HWIN + p] = u.y;
    }
}

// ---------------------------------------------------------------------------
// Copy x2 into concat buffer channels [0,256)
__global__ void k_copy(const float* __restrict__ x2) {
    int i = blockIdx.x * 256 + threadIdx.x;       // float4 index
    if (i >= B_ * 256 * (HW / 4)) return;
    int b = i >> 18;
    int c = (i >> 10) & 255;
    int p4 = i & 1023;
    ((float4*)g_x)[((b * 512) + c) * 1024 + p4] =
        ((const float4*)x2)[i];
}

// ---------------------------------------------------------------------------
// Bilinear upsample 32->64 (align_corners) of g_t, add up_b, write into
// concat buffer channels [256,512)
__global__ void k_upsample(const float* __restrict__ up_b) {
    int idx = blockIdx.x * 256 + threadIdx.x;
    if (idx >= B_ * CO * HW) return;
    int p = idx & (HW - 1);
    int c = (idx >> 12) & (CO - 1);
    int b = idx >> 20;
    int h = p >> 6, w = p & 63;
    const float scale = 31.0f / 63.0f;
    float fh = h * scale;
    int i0 = (int)floorf(fh); if (i0 > 30) i0 = 30;
    float wy = fh - (float)i0;
    float fw = w * scale;
    int j0 = (int)floorf(fw); if (j0 > 30) j0 = 30;
    float wx = fw - (float)j0;
    const float* t = g_t + (idx >> 12) * HWIN;
    float v00 = t[i0 * 32 + j0];
    float v01 = t[i0 * 32 + j0 + 1];
    float v10 = t[(i0 + 1) * 32 + j0];
    float v11 = t[(i0 + 1) * 32 + j0 + 1];
    float v = (1.f - wy) * ((1.f - wx) * v00 + wx * v01) +
              wy * ((1.f - wx) * v10 + wx * v11);
    g_x[((b * 512) + 256 + c) * HW + p] = v + up_b[c];
}

// ---------------------------------------------------------------------------
// Offset conv partials: 3x3 pad=1, 512->18, ci split into 4 chunks of 128.
__global__ void k_offconv(const float* __restrict__ off_w) {
    __shared__ __align__(16) float xr[8][3][66];
    __shared__ __align__(16) float wsh[8][9 * 18];  // [ciL][tap*18 + c]
    int b = blockIdx.z, cc = blockIdx.y, h = blockIdx.x, t = threadIdx.x;
    int ci0 = cc * 128;
    ull a[9];
#pragma unroll
    for (int c = 0; c < 9; c++) a[c] = 0ull;
    for (int s8 = 0; s8 < 128; s8 += 8) {
        for (int idx = t; idx < 8 * 198; idx += 64) {
            int ciL = idx / 198;
            int rem = idx - ciL * 198;
            int r = rem / 66;
            int c66 = rem - r * 66;
            int cw = c66 - 1;
            int y = h - 1 + r;
            const float* pl = g_x + ((b * 512 + ci0 + s8 + ciL) << 12);
            xr[ciL][r][c66] = (y >= 0 && y < 64 && cw >= 0 && cw < 64)
                                  ? pl[y * 64 + cw] : 0.f;
        }
        for (int idx = t; idx < 8 * 162; idx += 64) {
            int ciL = idx / 162;
            int rem = idx - ciL * 162;
            int tap = rem / 18;
            int c = rem - tap * 18;
            int ci = ci0 + s8 + ciL;
            wsh[ciL][rem] = off_w[(c * 512 + ci) * 9 + tap];
        }
        __syncthreads();
#pragma unroll 2
        for (int ciL = 0; ciL < 8; ciL++) {
#pragma unroll
            for (int tap = 0; tap < 9; tap++) {
                float xv = xr[ciL][tap / 3][t + tap % 3];
                ull xv2 = pack2(xv, xv);
                const ull* wr = (const ull*)&wsh[ciL][tap * 18];
#pragma unroll
                for (int c2 = 0; c2 < 9; c2++) fma2(a[c2], wr[c2], xv2);
            }
        }
        __syncthreads();
    }
#pragma unroll
    for (int c2 = 0; c2 < 9; c2++) {
        float2 u = unpack2(a[c2]);
        float* dst = g_offp + ((b * 4 + cc) * OFFC) * HW + h * 64 + t;
        dst[(2 * c2) * HW] = u.x;
        dst[(2 * c2 + 1) * HW] = u.y;
    }
}

// Reduce 4 ci-chunk partials + bias
__global__ void k_offred(const float* __restrict__ off_b) {
    int idx = blockIdx.x * 256 + threadIdx.x;
    if (idx >= B_ * OFFC * HW) return;
    int b = idx / (OFFC * HW);
    int rem = idx - b * OFFC * HW;
    int c = rem >> 12;
    float s = off_b[c];
#pragma unroll
    for (int cc = 0; cc < 4; cc++)
        s += g_offp[(b * 4 + cc) * OFFC * HW + rem];
    g_off[idx] = s;
}

// ---------------------------------------------------------------------------
// Transpose def_w (co,ci,k) -> (k,ci,co); coalesced reads
__global__ void k_wt(const float* __restrict__ def_w) {
    int i = blockIdx.x * 256 + threadIdx.x;
    if (i >= K2 * CC * CO) return;
    float v = def_w[i];           // i = (co*512 + ci)*9 + k
    int k = i % 9;
    int t9 = i / 9;
    int ci = t9 & 511;
    int co = t9 >> 9;
    g_wT[(k * CC + ci) * CO + co] = v;
}

// ---------------------------------------------------------------------------
// Deformable conv. Block = (16-pixel tile, batch); 64 threads.
// Thread t owns co = 4t..4t+3 (weights = one float4), 16-pixel accumulators.
// FMA:LDS ratio 4:1 via pixel-pair FFMA2.
#define PIX 16
#define CICHUNK 64
__global__ void __launch_bounds__(64) k_deform(const float* __restrict__ def_b) {
    __shared__ __align__(16) float v_sh[CICHUNK][PIX];
    __shared__ int4 offs[PIX];
    __shared__ float4 cws[PIX];
    int b = blockIdx.y;
    int p0 = blockIdx.x * PIX;
    int t = threadIdx.x;
    ull acc[4][8];
#pragma unroll
    for (int j = 0; j < 4; j++)
#pragma unroll
        for (int q = 0; q < 8; q++) acc[j][q] = 0ull;
    const float* offp = g_off + b * OFFC * HW;
    const float* xb = g_x + (b * 512) * HW;

    for (int k = 0; k < 9; k++) {
        if (t < PIX) {
            int p = p0 + t;
            int h = p >> 6, w = p & 63;
            float dy = offp[(2 * k) * HW + p];
            float dx = offp[(2 * k + 1) * HW + p];
            float py = (float)h + (float)(k / 3) - 1.f + dy;
            float px = (float)w + (float)(k % 3) - 1.f + dx;
            float fy = floorf(py), fx = floorf(px);
            float wy = py - fy, wx = px - fx;
            int y0 = (int)fy, x0 = (int)fx;
            int y1 = y0 + 1, x1 = x0 + 1;
            bool vy0 = (unsigned)y0 < 64u, vy1 = (unsigned)y1 < 64u;
            bool vx0 = (unsigned)x0 < 64u, vx1 = (unsigned)x1 < 64u;
            int y0c = min(max(y0, 0), 63), y1c = min(max(y1, 0), 63);
            int x0c = min(max(x0, 0), 63), x1c = min(max(x1, 0), 63);
            cws[t] = make_float4((vy0 && vx0) ? (1.f - wy) * (1.f - wx) : 0.f,
                                 (vy0 && vx1) ? (1.f - wy) * wx : 0.f,
                                 (vy1 && vx0) ? wy * (1.f - wx) : 0.f,
                                 (vy1 && vx1) ? wy * wx : 0.f);
            offs[t] = make_int4(y0c * 64 + x0c, y0c * 64 + x1c,
                                y1c * 64 + x0c, y1c * 64 + x1c);
        }
        __syncthreads();
        for (int c0 = 0; c0 < CC; c0 += CICHUNK) {
            const float* base = xb + c0 * HW;
            // gather: 64 ci x 16 pix = 1024 entries / 64 threads = 16 each
#pragma unroll
            for (int j = 0; j < (CICHUNK * PIX) / 64; j++) {
                int e = t + j * 64;
                int pi = e & (PIX - 1);
                int cl = e >> 4;
                int4 o = offs[pi];
                float4 cw = cws[pi];
                const float* pl = base + (cl << 12);
                v_sh[cl][pi] = cw.x * __ldg(pl + o.x) + cw.y * __ldg(pl + o.y) +
                               cw.z * __ldg(pl + o.z) + cw.w * __ldg(pl + o.w);
            }
            __syncthreads();
            const float4* wp = (const float4*)(g_wT + (k * CC + c0) * CO) + t;
#pragma unroll 4
            for (int cl = 0; cl < CICHUNK; cl++) {
                float4 w = __ldg(wp + cl * 64);
                ull w0 = pack2(w.x, w.x);
                ull w1 = pack2(w.y, w.y);
                ull w2 = pack2(w.z, w.z);
                ull w3 = pack2(w.w, w.w);
                const ull* vv = (const ull*)v_sh[cl];
#pragma unroll
                for (int q = 0; q < 8; q++) {
                    ull bq = vv[q];
                    fma2(acc[0][q], w0, bq);
                    fma2(acc[1][q], w1, bq);
                    fma2(acc[2][q], w2, bq);
                    fma2(acc[3][q], w3, bq);
                }
            }
            __syncthreads();
        }
    }
#pragma unroll
    for (int j = 0; j < 4; j++) {
        int co = 4 * t + j;
        float bb = def_b[co];
        float* o = g_dc + (b * CO + co) * HW + p0;
#pragma unroll
        for (int q = 0; q < 4; q++) {
            float2 u0 = unpack2(acc[j][2 * q]);
            float2 u1 = unpack2(acc[j][2 * q + 1]);
            ((float4*)o)[q] = make_float4(u0.x + bb, u0.y + bb,
                                          u1.x + bb, u1.y + bb);
        }
    }
}

// ---------------------------------------------------------------------------
// BN stats: per-channel mean/rstd (deterministic tree reduction)
__global__ void k_stats() {
    int co = blockIdx.x, t = threadIdx.x;
    const float* p0 = g_dc + co * HW;
    const float* p1 = g_dc + (CO + co) * HW;
    float s = 0.f, s2 = 0.f;
    for (int i = t; i < HW; i += 256) {
        float v = p0[i]; s += v; s2 += v * v;
        v = p1[i]; s += v; s2 += v * v;
    }
    __shared__ float sh[256], sh2[256];
    sh[t] = s; sh2[t] = s2;
    __syncthreads();
    for (int o = 128; o > 0; o >>= 1) {
        if (t < o) { sh[t] += sh[t + o]; sh2[t] += sh2[t + o]; }
        __syncthreads();
    }
    if (t == 0) {
        float m = sh[0] * (1.f / 8192.f);
        float var = sh2[0] * (1.f / 8192.f) - m * m;
        g_stats[co] = m;
        g_stats[CO + co] = rsqrtf(var + 1e-5f);
    }
}

// ---------------------------------------------------------------------------
// Shortcut 1x1 conv (on concat buffer) + BN apply + relu
__global__ void k_final(const float* __restrict__ sc_w,
                        const float* __restrict__ sc_b,
                        const float* __restrict__ gamma,
                        const float* __restrict__ beta,
                        float* __restrict__ out) {
    __shared__ __align__(16) float ws[8 * 512];   // [ci][j]
    int b = blockIdx.z;
    int co0 = blockIdx.y * 8;
    int p = blockIdx.x * 128 + threadIdx.x;
    for (int i = threadIdx.x; i < 4096; i += 128) {
        int j = i >> 9, ci = i & 511;
        ws[ci * 8 + j] = sc_w[(co0 + j) * 512 + ci];
    }
    __syncthreads();
    ull a[4] = {0ull, 0ull, 0ull, 0ull};
    const float* xp = g_x + b * 512 * HW + p;
#pragma unroll 4
    for (int ci = 0; ci < 512; ci++) {
        float xv = __ldg(xp + ci * HW);
        ull xv2 = pack2(xv, xv);
        const ull* wr = (const ull*)(ws + ci * 8);
        fma2(a[0], wr[0], xv2);
        fma2(a[1], wr[1], xv2);
        fma2(a[2], wr[2], xv2);
        fma2(a[3], wr[3], xv2);
    }
#pragma unroll
    for (int jp = 0; jp < 4; jp++) {
        float2 u = unpack2(a[jp]);
#pragma unroll
        for (int half = 0; half < 2; half++) {
            int co = co0 + 2 * jp + half;
            float accv = half ? u.y : u.x;
            float m = g_stats[co], r = g_stats[CO + co];
            float v = (g_dc[(b * CO + co) * HW + p] - m) * r * gamma[co] +
                      beta[co] + accv + sc_b[co];
            out[(b * CO + co) * HW + p] = fmaxf(v, 0.f);
        }
    }
}

// ---------------------------------------------------------------------------
extern "C" void kernel_launch(void* const* d_in, const int* in_sizes, int n_in,
                              void* d_out, int out_size) {
    const float* x1    = (const float*)d_in[0];
    const float* x2    = (const float*)d_in[1];
    const float* up_w  = (const float*)d_in[2];
    const float* up_b  = (const float*)d_in[3];
    const float* off_w = (const float*)d_in[4];
    const float* off_b = (const float*)d_in[5];
    const float* def_w = (const float*)d_in[6];
    const float* def_b = (const float*)d_in[7];
    const float* bn_g  = (const float*)d_in[8];
    const float* bn_b  = (const float*)d_in[9];
    const float* sc_w  = (const float*)d_in[10];
    const float* sc_b  = (const float*)d_in[11];
    float* out = (float*)d_out;

    k_upconv<<<dim3(HWIN / 128, CO / 8, B_), 128>>>(x1, up_w);
    k_copy<<<(B_ * 256 * (HW / 4) + 255) / 256, 256>>>(x2);
    k_upsample<<<(B_ * CO * HW + 255) / 256, 256>>>(up_b);
    k_wt<<<(K2 * CC * CO + 255) / 256, 256>>>(def_w);
    k_offconv<<<dim3(H_, 4, B_), 64>>>(off_w);
    k_offred<<<(B_ * OFFC * HW + 255) / 256, 256>>>(off_b);
    k_deform<<<dim3(HW / PIX, B_), 64>>>(def_b);
    k_stats<<<CO, 256>>>();
    k_final<<<dim3(HW / 128, CO / 8, B_), 128>>>(sc_w, sc_b, bn_g, bn_b, out);
}

// round 4
// speedup vs baseline: 1.3412x; 1.3412x over previous
#include <cuda_runtime.h>
#include <math.h>

// Problem constants
#define B_ 2
#define CC 512      // concat channels
#define CO 256      // output channels
#define C1 512      // x1 channels
#define H_ 64
#define W_ 64
#define HW 4096
#define HWIN 1024
#define OFFC 18
#define K2 9

typedef unsigned long long ull;

// Packed f32x2 helpers (Blackwell FFMA2 path)
__device__ __forceinline__ ull pack2(float lo, float hi) {
    ull r; asm("mov.b64 %0, {%1,%2};" : "=l"(r) : "f"(lo), "f"(hi)); return r;
}
__device__ __forceinline__ void fma2(ull& d, ull a, ull b) {
    asm("fma.rn.f32x2 %0, %1, %2, %0;" : "+l"(d) : "l"(a), "l"(b));
}
__device__ __forceinline__ float2 unpack2(ull v) {
    float2 r; asm("mov.b64 {%0,%1}, %2;" : "=f"(r.x), "=f"(r.y) : "l"(v)); return r;
}

// Scratch (device globals; no runtime allocation)
__device__ float g_t[B_ * CO * HWIN];          // 1x1-conv'd x1 @ 32x32 (no bias)
__device__ __align__(16) float g_x[B_ * CC * HW];  // concat tensor [b][512][64][64]
__device__ float g_off[B_ * OFFC * HW];        // final offset field
__device__ float g_offp[B_ * 4 * OFFC * HW];   // offset partials (4 ci-chunks)
__device__ float g_dc[B_ * CO * HW];           // deform conv output (+def_b)
__device__ __align__(16) float g_wT[K2 * CC * CO + 256];  // def_w [k][ci][co] (+pad)
__device__ float g_stats[2 * CO];              // mean, rstd per channel

// ---------------------------------------------------------------------------
// 1x1 conv on x1 at 32x32 (transposed weight staging + FFMA2)
__global__ void k_upconv(const float* __restrict__ x1,
                         const float* __restrict__ up_w) {
    __shared__ __align__(16) float ws[8 * 512];   // [ci][j]
    int b = blockIdx.z;
    int co0 = blockIdx.y * 8;
    int p = blockIdx.x * 128 + threadIdx.x;
    for (int i = threadIdx.x; i < 4096; i += 128) {
        int j = i >> 9, ci = i & 511;
        ws[ci * 8 + j] = up_w[(co0 + j) * 512 + ci];
    }
    __syncthreads();
    ull a[4] = {0ull, 0ull, 0ull, 0ull};
    const float* xp = x1 + b * C1 * HWIN + p;
#pragma unroll 4
    for (int ci = 0; ci < 512; ci++) {
        float xv = __ldg(xp + ci * HWIN);
        ull xv2 = pack2(xv, xv);
        const ull* wr = (const ull*)(ws + ci * 8);
        fma2(a[0], wr[0], xv2);
        fma2(a[1], wr[1], xv2);
        fma2(a[2], wr[2], xv2);
        fma2(a[3], wr[3], xv2);
    }
#pragma unroll
    for (int jp = 0; jp < 4; jp++) {
        float2 u = unpack2(a[jp]);
        g_t[(b * CO + co0 + 2 * jp) * HWIN + p] = u.x;
        g_t[(b * CO + co0 + 2 * jp + 1) * HWIN + p] = u.y;
    }
}

// ---------------------------------------------------------------------------
// Copy x2 into concat buffer channels [0,256)
__global__ void k_copy(const float* __restrict__ x2) {
    int i = blockIdx.x * 256 + threadIdx.x;       // float4 index
    if (i >= B_ * 256 * (HW / 4)) return;
    int b = i >> 18;
    int c = (i >> 10) & 255;
    int p4 = i & 1023;
    ((float4*)g_x)[((b * 512) + c) * 1024 + p4] =
        ((const float4*)x2)[i];
}

// ---------------------------------------------------------------------------
// Bilinear upsample 32->64 (align_corners) of g_t, add up_b -> channels [256,512)
__global__ void k_upsample(const float* __restrict__ up_b) {
    int idx = blockIdx.x * 256 + threadIdx.x;
    if (idx >= B_ * CO * HW) return;
    int p = idx & (HW - 1);
    int c = (idx >> 12) & (CO - 1);
    int b = idx >> 20;
    int h = p >> 6, w = p & 63;
    const float scale = 31.0f / 63.0f;
    float fh = h * scale;
    int i0 = (int)floorf(fh); if (i0 > 30) i0 = 30;
    float wy = fh - (float)i0;
    float fw = w * scale;
    int j0 = (int)floorf(fw); if (j0 > 30) j0 = 30;
    float wx = fw - (float)j0;
    const float* t = g_t + (idx >> 12) * HWIN;
    float v00 = t[i0 * 32 + j0];
    float v01 = t[i0 * 32 + j0 + 1];
    float v10 = t[(i0 + 1) * 32 + j0];
    float v11 = t[(i0 + 1) * 32 + j0 + 1];
    float v = (1.f - wy) * ((1.f - wx) * v00 + wx * v01) +
              wy * ((1.f - wx) * v10 + wx * v11);
    g_x[((b * 512) + 256 + c) * HW + p] = v + up_b[c];
}

// ---------------------------------------------------------------------------
// Offset conv partials: 3x3 pad=1, 512->18, ci split into 4 chunks of 128.
__global__ void k_offconv(const float* __restrict__ off_w) {
    __shared__ __align__(16) float xr[8][3][66];
    __shared__ __align__(16) float wsh[8][9 * 18];  // [ciL][tap*18 + c]
    int b = blockIdx.z, cc = blockIdx.y, h = blockIdx.x, t = threadIdx.x;
    int ci0 = cc * 128;
    ull a[9];
#pragma unroll
    for (int c = 0; c < 9; c++) a[c] = 0ull;
    for (int s8 = 0; s8 < 128; s8 += 8) {
        for (int idx = t; idx < 8 * 198; idx += 64) {
            int ciL = idx / 198;
            int rem = idx - ciL * 198;
            int r = rem / 66;
            int c66 = rem - r * 66;
            int cw = c66 - 1;
            int y = h - 1 + r;
            const float* pl = g_x + ((b * 512 + ci0 + s8 + ciL) << 12);
            xr[ciL][r][c66] = (y >= 0 && y < 64 && cw >= 0 && cw < 64)
                                  ? pl[y * 64 + cw] : 0.f;
        }
        for (int idx = t; idx < 8 * 162; idx += 64) {
            int ciL = idx / 162;
            int rem = idx - ciL * 162;
            int tap = rem / 18;
            int c = rem - tap * 18;
            int ci = ci0 + s8 + ciL;
            wsh[ciL][rem] = off_w[(c * 512 + ci) * 9 + tap];
        }
        __syncthreads();
#pragma unroll 2
        for (int ciL = 0; ciL < 8; ciL++) {
#pragma unroll
            for (int tap = 0; tap < 9; tap++) {
                float xv = xr[ciL][tap / 3][t + tap % 3];
                ull xv2 = pack2(xv, xv);
                const ull* wr = (const ull*)&wsh[ciL][tap * 18];
#pragma unroll
                for (int c2 = 0; c2 < 9; c2++) fma2(a[c2], wr[c2], xv2);
            }
        }
        __syncthreads();
    }
#pragma unroll
    for (int c2 = 0; c2 < 9; c2++) {
        float2 u = unpack2(a[c2]);
        float* dst = g_offp + ((b * 4 + cc) * OFFC) * HW + h * 64 + t;
        dst[(2 * c2) * HW] = u.x;
        dst[(2 * c2 + 1) * HW] = u.y;
    }
}

// Reduce 4 ci-chunk partials + bias
__global__ void k_offred(const float* __restrict__ off_b) {
    int idx = blockIdx.x * 256 + threadIdx.x;
    if (idx >= B_ * OFFC * HW) return;
    int b = idx / (OFFC * HW);
    int rem = idx - b * OFFC * HW;
    int c = rem >> 12;
    float s = off_b[c];
#pragma unroll
    for (int cc = 0; cc < 4; cc++)
        s += g_offp[(b * 4 + cc) * OFFC * HW + rem];
    g_off[idx] = s;
}

// ---------------------------------------------------------------------------
// Transpose def_w (co,ci,k) -> (k,ci,co); write-coalesced (R2 version)
__global__ void k_wt(const float* __restrict__ def_w) {
    int i = blockIdx.x * 256 + threadIdx.x;
    if (i >= K2 * CC * CO) return;
    int co = i & 255;
    int ci = (i >> 8) & 511;
    int k = i >> 17;
    g_wT[i] = def_w[(co * 512 + ci) * 9 + k];
}

// ---------------------------------------------------------------------------
// Deformable conv. Block = (32-pixel tile, batch); 256 threads (8 warps).
// Thread t: tco = t&63 -> co quad 4*tco (float4 weight), tp = t>>6 -> 8-pixel
// slice. acc = 4 co x 4 ull. FMA:LDS = 4:1 via pixel-pair FFMA2.
#define PIX 32
#define CICHUNK 64
__global__ void __launch_bounds__(256) k_deform(const float* __restrict__ def_b) {
    __shared__ __align__(16) float v_sh[CICHUNK][PIX];
    __shared__ int4 offs[PIX];
    __shared__ float4 cws[PIX];
    int b = blockIdx.y;
    int p0 = blockIdx.x * PIX;
    int t = threadIdx.x;
    int tco = t & 63;
    int tp = t >> 6;             // 0..3, pixels tp*8 .. tp*8+7
    ull acc[4][4];
#pragma unroll
    for (int j = 0; j < 4; j++)
#pragma unroll
        for (int q = 0; q < 4; q++) acc[j][q] = 0ull;
    const float* offp = g_off + b * OFFC * HW;
    const float* xb = g_x + (b * 512) * HW;

    for (int k = 0; k < 9; k++) {
        if (t < PIX) {
            int p = p0 + t;
            int h = p >> 6, w = p & 63;
            float dy = offp[(2 * k) * HW + p];
            float dx = offp[(2 * k + 1) * HW + p];
            float py = (float)h + (float)(k / 3) - 1.f + dy;
            float px = (float)w + (float)(k % 3) - 1.f + dx;
            float fy = floorf(py), fx = floorf(px);
            float wy = py - fy, wx = px - fx;
            int y0 = (int)fy, x0 = (int)fx;
            int y1 = y0 + 1, x1 = x0 + 1;
            bool vy0 = (unsigned)y0 < 64u, vy1 = (unsigned)y1 < 64u;
            bool vx0 = (unsigned)x0 < 64u, vx1 = (unsigned)x1 < 64u;
            int y0c = min(max(y0, 0), 63), y1c = min(max(y1, 0), 63);
            int x0c = min(max(x0, 0), 63), x1c = min(max(x1, 0), 63);
            cws[t] = make_float4((vy0 && vx0) ? (1.f - wy) * (1.f - wx) : 0.f,
                                 (vy0 && vx1) ? (1.f - wy) * wx : 0.f,
                                 (vy1 && vx0) ? wy * (1.f - wx) : 0.f,
                                 (vy1 && vx1) ? wy * wx : 0.f);
            offs[t] = make_int4(y0c * 64 + x0c, y0c * 64 + x1c,
                                y1c * 64 + x0c, y1c * 64 + x1c);
        }
        __syncthreads();
        for (int c0 = 0; c0 < CC; c0 += CICHUNK) {
            const float* base = xb + c0 * HW;
            // gather: 64 ci x 32 pix = 2048 entries / 256 threads = 8 each
#pragma unroll
            for (int j = 0; j < (CICHUNK * PIX) / 256; j++) {
                int e = t + j * 256;
                int pi = e & (PIX - 1);
                int cl = e >> 5;
                int4 o = offs[pi];
                float4 cw = cws[pi];
                const float* pl = base + (cl << 12);
                v_sh[cl][pi] = cw.x * __ldg(pl + o.x) + cw.y * __ldg(pl + o.y) +
                               cw.z * __ldg(pl + o.z) + cw.w * __ldg(pl + o.w);
            }
            __syncthreads();
            const float4* wp = (const float4*)(g_wT + (k * CC + c0) * CO) + tco;
#pragma unroll 4
            for (int cl = 0; cl < CICHUNK; cl++) {
                float4 w = __ldg(wp + cl * 64);
                ull w0 = pack2(w.x, w.x);
                ull w1 = pack2(w.y, w.y);
                ull w2 = pack2(w.z, w.z);
                ull w3 = pack2(w.w, w.w);
                const ull* vv = (const ull*)&v_sh[cl][tp * 8];
#pragma unroll
                for (int q = 0; q < 4; q++) {
                    ull bq = vv[q];
                    fma2(acc[0][q], w0, bq);
                    fma2(acc[1][q], w1, bq);
                    fma2(acc[2][q], w2, bq);
                    fma2(acc[3][q], w3, bq);
                }
            }
            __syncthreads();
        }
    }
#pragma unroll
    for (int j = 0; j < 4; j++) {
        int co = 4 * tco + j;
        float bb = def_b[co];
        float* o = g_dc + (b * CO + co) * HW + p0 + tp * 8;
#pragma unroll
        for (int q = 0; q < 2; q++) {
            float2 u0 = unpack2(acc[j][2 * q]);
            float2 u1 = unpack2(acc[j][2 * q + 1]);
            ((float4*)o)[q] = make_float4(u0.x + bb, u0.y + bb,
                                          u1.x + bb, u1.y + bb);
        }
    }
}

// ---------------------------------------------------------------------------
// BN stats: per-channel mean/rstd (deterministic tree reduction)
__global__ void k_stats() {
    int co = blockIdx.x, t = threadIdx.x;
    const float* p0 = g_dc + co * HW;
    const float* p1 = g_dc + (CO + co) * HW;
    float s = 0.f, s2 = 0.f;
    for (int i = t; i < HW; i += 256) {
        float v = p0[i]; s += v; s2 += v * v;
        v = p1[i]; s += v; s2 += v * v;
    }
    __shared__ float sh[256], sh2[256];
    sh[t] = s; sh2[t] = s2;
    __syncthreads();
    for (int o = 128; o > 0; o >>= 1) {
        if (t < o) { sh[t] += sh[t + o]; sh2[t] += sh2[t + o]; }
        __syncthreads();
    }
    if (t == 0) {
        float m = sh[0] * (1.f / 8192.f);
        float var = sh2[0] * (1.f / 8192.f) - m * m;
        g_stats[co] = m;
        g_stats[CO + co] = rsqrtf(var + 1e-5f);
    }
}

// ---------------------------------------------------------------------------
// Shortcut 1x1 conv (on concat buffer) + BN apply + relu
__global__ void k_final(const float* __restrict__ sc_w,
                        const float* __restrict__ sc_b,
                        const float* __restrict__ gamma,
                        const float* __restrict__ beta,
                        float* __restrict__ out) {
    __shared__ __align__(16) float ws[8 * 512];   // [ci][j]
    int b = blockIdx.z;
    int co0 = blockIdx.y * 8;
    int p = blockIdx.x * 128 + threadIdx.x;
    for (int i = threadIdx.x; i < 4096; i += 128) {
        int j = i >> 9, ci = i & 511;
        ws[ci * 8 + j] = sc_w[(co0 + j) * 512 + ci];
    }
    __syncthreads();
    ull a[4] = {0ull, 0ull, 0ull, 0ull};
    const float* xp = g_x + b * 512 * HW + p;
#pragma unroll 4
    for (int ci = 0; ci < 512; ci++) {
        float xv = __ldg(xp + ci * HW);
        ull xv2 = pack2(xv, xv);
        const ull* wr = (const ull*)(ws + ci * 8);
        fma2(a[0], wr[0], xv2);
        fma2(a[1], wr[1], xv2);
        fma2(a[2], wr[2], xv2);
        fma2(a[3], wr[3], xv2);
    }
#pragma unroll
    for (int jp = 0; jp < 4; jp++) {
        float2 u = unpack2(a[jp]);
#pragma unroll
        for (int half = 0; half < 2; half++) {
            int co = co0 + 2 * jp + half;
            float accv = half ? u.y : u.x;
            float m = g_stats[co], r = g_stats[CO + co];
            float v = (g_dc[(b * CO + co) * HW + p] - m) * r * gamma[co] +
                      beta[co] + accv + sc_b[co];
            out[(b * CO + co) * HW + p] = fmaxf(v, 0.f);
        }
    }
}

// ---------------------------------------------------------------------------
extern "C" void kernel_launch(void* const* d_in, const int* in_sizes, int n_in,
                              void* d_out, int out_size) {
    const float* x1    = (const float*)d_in[0];
    const float* x2    = (const float*)d_in[1];
    const float* up_w  = (const float*)d_in[2];
    const float* up_b  = (const float*)d_in[3];
    const float* off_w = (const float*)d_in[4];
    const float* off_b = (const float*)d_in[5];
    const float* def_w = (const float*)d_in[6];
    const float* def_b = (const float*)d_in[7];
    const float* bn_g  = (const float*)d_in[8];
    const float* bn_b  = (const float*)d_in[9];
    const float* sc_w  = (const float*)d_in[10];
    const float* sc_b  = (const float*)d_in[11];
    float* out = (float*)d_out;

    k_upconv<<<dim3(HWIN / 128, CO / 8, B_), 128>>>(x1, up_w);
    k_copy<<<(B_ * 256 * (HW / 4) + 255) / 256, 256>>>(x2);
    k_upsample<<<(B_ * CO * HW + 255) / 256, 256>>>(up_b);
    k_wt<<<(K2 * CC * CO + 255) / 256, 256>>>(def_w);
    k_offconv<<<dim3(H_, 4, B_), 64>>>(off_w);
    k_offred<<<(B_ * OFFC * HW + 255) / 256, 256>>>(off_b);
    k_deform<<<dim3(HW / PIX, B_), 256>>>(def_b);
    k_stats<<<CO, 256>>>();
    k_final<<<dim3(HW / 128, CO / 8, B_), 128>>>(sc_w, sc_b, bn_g, bn_b, out);
}

// round 5
// speedup vs baseline: 1.4204x; 1.0590x over previous
#include <cuda_runtime.h>
#include <math.h>

// Problem constants
#define B_ 2
#define CC 512      // concat channels
#define CO 256      // output channels
#define C1 512      // x1 channels
#define H_ 64
#define W_ 64
#define HW 4096
#define HWIN 1024
#define OFFC 18
#define K2 9

typedef unsigned long long ull;

// Packed f32x2 helpers (Blackwell FFMA2 path)
__device__ __forceinline__ ull pack2(float lo, float hi) {
    ull r; asm("mov.b64 %0, {%1,%2};" : "=l"(r) : "f"(lo), "f"(hi)); return r;
}
__device__ __forceinline__ void fma2(ull& d, ull a, ull b) {
    asm("fma.rn.f32x2 %0, %1, %2, %0;" : "+l"(d) : "l"(a), "l"(b));
}
__device__ __forceinline__ float2 unpack2(ull v) {
    float2 r; asm("mov.b64 {%0,%1}, %2;" : "=f"(r.x), "=f"(r.y) : "l"(v)); return r;
}

// Scratch (device globals; no runtime allocation)
__device__ float g_t[B_ * CO * HWIN];          // 1x1-conv'd x1 @ 32x32 (no bias)
__device__ __align__(16) float g_x[B_ * CC * HW];  // concat tensor [b][512][64][64]
__device__ float g_off[B_ * OFFC * HW];        // final offset field
__device__ float g_offp[B_ * 4 * OFFC * HW];   // offset partials (4 ci-chunks)
__device__ float g_dc[B_ * CO * HW];           // deform conv output (+def_b)
__device__ __align__(16) float g_wT[K2 * CC * CO + 256];  // def_w [k][ci][co] (+pad)
__device__ float g_stats[2 * CO];              // mean, rstd per channel

// ---------------------------------------------------------------------------
// 1x1 conv on x1 at 32x32 (transposed weight staging + FFMA2)
__global__ void k_upconv(const float* __restrict__ x1,
                         const float* __restrict__ up_w) {
    __shared__ __align__(16) float ws[8 * 512];   // [ci][j]
    int b = blockIdx.z;
    int co0 = blockIdx.y * 8;
    int p = blockIdx.x * 128 + threadIdx.x;
    for (int i = threadIdx.x; i < 4096; i += 128) {
        int j = i >> 9, ci = i & 511;
        ws[ci * 8 + j] = up_w[(co0 + j) * 512 + ci];
    }
    __syncthreads();
    ull a[4] = {0ull, 0ull, 0ull, 0ull};
    const float* xp = x1 + b * C1 * HWIN + p;
#pragma unroll 4
    for (int ci = 0; ci < 512; ci++) {
        float xv = __ldg(xp + ci * HWIN);
        ull xv2 = pack2(xv, xv);
        const ull* wr = (const ull*)(ws + ci * 8);
        fma2(a[0], wr[0], xv2);
        fma2(a[1], wr[1], xv2);
        fma2(a[2], wr[2], xv2);
        fma2(a[3], wr[3], xv2);
    }
#pragma unroll
    for (int jp = 0; jp < 4; jp++) {
        float2 u = unpack2(a[jp]);
        g_t[(b * CO + co0 + 2 * jp) * HWIN + p] = u.x;
        g_t[(b * CO + co0 + 2 * jp + 1) * HWIN + p] = u.y;
    }
}

// ---------------------------------------------------------------------------
// Copy x2 into concat buffer channels [0,256)
__global__ void k_copy(const float* __restrict__ x2) {
    int i = blockIdx.x * 256 + threadIdx.x;       // float4 index
    if (i >= B_ * 256 * (HW / 4)) return;
    int b = i >> 18;
    int c = (i >> 10) & 255;
    int p4 = i & 1023;
    ((float4*)g_x)[((b * 512) + c) * 1024 + p4] =
        ((const float4*)x2)[i];
}

// ---------------------------------------------------------------------------
// Bilinear upsample 32->64 (align_corners) of g_t, add up_b -> channels [256,512)
__global__ void k_upsample(const float* __restrict__ up_b) {
    int idx = blockIdx.x * 256 + threadIdx.x;
    if (idx >= B_ * CO * HW) return;
    int p = idx & (HW - 1);
    int c = (idx >> 12) & (CO - 1);
    int b = idx >> 20;
    int h = p >> 6, w = p & 63;
    const float scale = 31.0f / 63.0f;
    float fh = h * scale;
    int i0 = (int)floorf(fh); if (i0 > 30) i0 = 30;
    float wy = fh - (float)i0;
    float fw = w * scale;
    int j0 = (int)floorf(fw); if (j0 > 30) j0 = 30;
    float wx = fw - (float)j0;
    const float* t = g_t + (idx >> 12) * HWIN;
    float v00 = t[i0 * 32 + j0];
    float v01 = t[i0 * 32 + j0 + 1];
    float v10 = t[(i0 + 1) * 32 + j0];
    float v11 = t[(i0 + 1) * 32 + j0 + 1];
    float v = (1.f - wy) * ((1.f - wx) * v00 + wx * v01) +
              wy * ((1.f - wx) * v10 + wx * v11);
    g_x[((b * 512) + 256 + c) * HW + p] = v + up_b[c];
}

// ---------------------------------------------------------------------------
// Offset conv partials: 3x3 pad=1, 512->18, ci split into 4 chunks of 128.
__global__ void k_offconv(const float* __restrict__ off_w) {
    __shared__ __align__(16) float xr[8][3][66];
    __shared__ __align__(16) float wsh[8][9 * 18];  // [ciL][tap*18 + c]
    int b = blockIdx.z, cc = blockIdx.y, h = blockIdx.x, t = threadIdx.x;
    int ci0 = cc * 128;
    ull a[9];
#pragma unroll
    for (int c = 0; c < 9; c++) a[c] = 0ull;
    for (int s8 = 0; s8 < 128; s8 += 8) {
        for (int idx = t; idx < 8 * 198; idx += 64) {
            int ciL = idx / 198;
            int rem = idx - ciL * 198;
            int r = rem / 66;
            int c66 = rem - r * 66;
            int cw = c66 - 1;
            int y = h - 1 + r;
            const float* pl = g_x + ((b * 512 + ci0 + s8 + ciL) << 12);
            xr[ciL][r][c66] = (y >= 0 && y < 64 && cw >= 0 && cw < 64)
                                  ? pl[y * 64 + cw] : 0.f;
        }
        for (int idx = t; idx < 8 * 162; idx += 64) {
            int ciL = idx / 162;
            int rem = idx - ciL * 162;
            int tap = rem / 18;
            int c = rem - tap * 18;
            int ci = ci0 + s8 + ciL;
            wsh[ciL][rem] = off_w[(c * 512 + ci) * 9 + tap];
        }
        __syncthreads();
#pragma unroll 2
        for (int ciL = 0; ciL < 8; ciL++) {
#pragma unroll
            for (int tap = 0; tap < 9; tap++) {
                float xv = xr[ciL][tap / 3][t + tap % 3];
                ull xv2 = pack2(xv, xv);
                const ull* wr = (const ull*)&wsh[ciL][tap * 18];
#pragma unroll
                for (int c2 = 0; c2 < 9; c2++) fma2(a[c2], wr[c2], xv2);
            }
        }
        __syncthreads();
    }
#pragma unroll
    for (int c2 = 0; c2 < 9; c2++) {
        float2 u = unpack2(a[c2]);
        float* dst = g_offp + ((b * 4 + cc) * OFFC) * HW + h * 64 + t;
        dst[(2 * c2) * HW] = u.x;
        dst[(2 * c2 + 1) * HW] = u.y;
    }
}

// Reduce 4 ci-chunk partials + bias
__global__ void k_offred(const float* __restrict__ off_b) {
    int idx = blockIdx.x * 256 + threadIdx.x;
    if (idx >= B_ * OFFC * HW) return;
    int b = idx / (OFFC * HW);
    int rem = idx - b * OFFC * HW;
    int c = rem >> 12;
    float s = off_b[c];
#pragma unroll
    for (int cc = 0; cc < 4; cc++)
        s += g_offp[(b * 4 + cc) * OFFC * HW + rem];
    g_off[idx] = s;
}

// ---------------------------------------------------------------------------
// Transpose def_w (co,ci,k) -> (k,ci,co)
__global__ void k_wt(const float* __restrict__ def_w) {
    int i = blockIdx.x * 256 + threadIdx.x;
    if (i >= K2 * CC * CO) return;
    int co = i & 255;
    int ci = (i >> 8) & 511;
    int k = i >> 17;
    g_wT[i] = def_w[(co * 512 + ci) * 9 + k];
}

// ---------------------------------------------------------------------------
// Deformable conv, software-pipelined.
// Block = (16-pixel tile, batch); 128 threads. Thread t: co quad 4*(t&63),
// pixel slice (t>>6)*8. 72 flat (tap,chunk) iterations, double-buffered v_sh,
// gather LDGs for iter i+1 issued before FMA of iter i. One sync/iteration.
#define PIX 16
#define CICHUNK 64
#define NITER 72
__global__ void __launch_bounds__(128) k_deform(const float* __restrict__ def_b) {
    __shared__ __align__(16) float v_sh[2][CICHUNK][PIX];
    __shared__ __align__(16) int4 offs[K2][PIX];
    __shared__ __align__(16) float4 cws[K2][PIX];
    int b = blockIdx.y;
    int p0 = blockIdx.x * PIX;
    int t = threadIdx.x;
    int tco = t & 63;
    int tp = t >> 6;                 // 0..1 -> pixels tp*8..tp*8+7
    const float* offp = g_off + b * OFFC * HW;
    const float* xb = g_x + (b * 512) * HW;

    // Precompute bilinear metadata for all 9 taps x 16 pixels
    for (int e = t; e < K2 * PIX; e += 128) {
        int k = e >> 4;
        int pi = e & 15;
        int p = p0 + pi;
        int h = p >> 6, w = p & 63;
        float dy = offp[(2 * k) * HW + p];
        float dx = offp[(2 * k + 1) * HW + p];
        float py = (float)h + (float)(k / 3) - 1.f + dy;
        float px = (float)w + (float)(k % 3) - 1.f + dx;
        float fy = floorf(py), fx = floorf(px);
        float wy = py - fy, wx = px - fx;
        int y0 = (int)fy, x0 = (int)fx;
        int y1 = y0 + 1, x1 = x0 + 1;
        bool vy0 = (unsigned)y0 < 64u, vy1 = (unsigned)y1 < 64u;
        bool vx0 = (unsigned)x0 < 64u, vx1 = (unsigned)x1 < 64u;
        int y0c = min(max(y0, 0), 63), y1c = min(max(y1, 0), 63);
        int x0c = min(max(x0, 0), 63), x1c = min(max(x1, 0), 63);
        cws[k][pi] = make_float4((vy0 && vx0) ? (1.f - wy) * (1.f - wx) : 0.f,
                                 (vy0 && vx1) ? (1.f - wy) * wx : 0.f,
                                 (vy1 && vx0) ? wy * (1.f - wx) : 0.f,
                                 (vy1 && vx1) ? wy * wx : 0.f);
        offs[k][pi] = make_int4(y0c * 64 + x0c, y0c * 64 + x1c,
                                y1c * 64 + x0c, y1c * 64 + x1c);
    }
    __syncthreads();

    ull acc[4][4];
#pragma unroll
    for (int j = 0; j < 4; j++)
#pragma unroll
        for (int q = 0; q < 4; q++) acc[j][q] = 0ull;

    float r[32];
    // Prologue: gather iteration 0 (k=0, c0=0) straight into buffer 0
#pragma unroll
    for (int j = 0; j < 8; j++) {
        int e = t + j * 128;
        int pi = e & 15;
        int cl = e >> 4;
        int4 o = offs[0][pi];
        const float* pl = xb + (cl << 12);
        r[4 * j + 0] = __ldg(pl + o.x);
        r[4 * j + 1] = __ldg(pl + o.y);
        r[4 * j + 2] = __ldg(pl + o.z);
        r[4 * j + 3] = __ldg(pl + o.w);
    }
#pragma unroll
    for (int j = 0; j < 8; j++) {
        int e = t + j * 128;
        int pi = e & 15;
        int cl = e >> 4;
        float4 cw = cws[0][pi];
        v_sh[0][cl][pi] = cw.x * r[4 * j] + cw.y * r[4 * j + 1] +
                          cw.z * r[4 * j + 2] + cw.w * r[4 * j + 3];
    }
    __syncthreads();

    int k = 0, c0 = 0;
    for (int i = 0; i < NITER; i++) {
        int buf = i & 1;
        int kn = k, c0n = c0 + CICHUNK;
        if (c0n == CC) { c0n = 0; kn = k + 1; }
        // Issue raw gather LDGs for iteration i+1 (latency hidden by FMA below)
        if (i + 1 < NITER) {
            const float* basen = xb + c0n * HW;
#pragma unroll
            for (int j = 0; j < 8; j++) {
                int e = t + j * 128;
                int pi = e & 15;
                int cl = e >> 4;
                int4 o = offs[kn][pi];
                const float* pl = basen + (cl << 12);
                r[4 * j + 0] = __ldg(pl + o.x);
                r[4 * j + 1] = __ldg(pl + o.y);
                r[4 * j + 2] = __ldg(pl + o.z);
                r[4 * j + 3] = __ldg(pl + o.w);
            }
        }
        // FMA phase on current buffer
        const float4* wp = (const float4*)(g_wT + (k * CC + c0) * CO) + tco;
#pragma unroll 4
        for (int cl = 0; cl < CICHUNK; cl++) {
            float4 w = __ldg(wp + cl * 64);
            ull w0 = pack2(w.x, w.x);
            ull w1 = pack2(w.y, w.y);
            ull w2 = pack2(w.z, w.z);
            ull w3 = pack2(w.w, w.w);
            const ull* vv = (const ull*)&v_sh[buf][cl][tp * 8];
#pragma unroll
            for (int q = 0; q < 4; q++) {
                ull bq = vv[q];
                fma2(acc[0][q], w0, bq);
                fma2(acc[1][q], w1, bq);
                fma2(acc[2][q], w2, bq);
                fma2(acc[3][q], w3, bq);
            }
        }
        // Combine gathered corners and store into the other buffer
        if (i + 1 < NITER) {
#pragma unroll
            for (int j = 0; j < 8; j++) {
                int e = t + j * 128;
                int pi = e & 15;
                int cl = e >> 4;
                float4 cw = cws[kn][pi];
                v_sh[buf ^ 1][cl][pi] = cw.x * r[4 * j] + cw.y * r[4 * j + 1] +
                                        cw.z * r[4 * j + 2] + cw.w * r[4 * j + 3];
            }
        }
        __syncthreads();
        k = kn; c0 = c0n;
    }

#pragma unroll
    for (int j = 0; j < 4; j++) {
        int co = 4 * tco + j;
        float bb = def_b[co];
        float* o = g_dc + (b * CO + co) * HW + p0 + tp * 8;
#pragma unroll
        for (int q = 0; q < 2; q++) {
            float2 u0 = unpack2(acc[j][2 * q]);
            float2 u1 = unpack2(acc[j][2 * q + 1]);
            ((float4*)o)[q] = make_float4(u0.x + bb, u0.y + bb,
                                          u1.x + bb, u1.y + bb);
        }
    }
}

// ---------------------------------------------------------------------------
// BN stats: per-channel mean/rstd (deterministic tree reduction)
__global__ void k_stats() {
    int co = blockIdx.x, t = threadIdx.x;
    const float* p0 = g_dc + co * HW;
    const float* p1 = g_dc + (CO + co) * HW;
    float s = 0.f, s2 = 0.f;
    for (int i = t; i < HW; i += 256) {
        float v = p0[i]; s += v; s2 += v * v;
        v = p1[i]; s += v; s2 += v * v;
    }
    __shared__ float sh[256], sh2[256];
    sh[t] = s; sh2[t] = s2;
    __syncthreads();
    for (int o = 128; o > 0; o >>= 1) {
        if (t < o) { sh[t] += sh[t + o]; sh2[t] += sh2[t + o]; }
        __syncthreads();
    }
    if (t == 0) {
        float m = sh[0] * (1.f / 8192.f);
        float var = sh2[0] * (1.f / 8192.f) - m * m;
        g_stats[co] = m;
        g_stats[CO + co] = rsqrtf(var + 1e-5f);
    }
}

// ---------------------------------------------------------------------------
// Shortcut 1x1 conv (on concat buffer) + BN apply + relu
__global__ void k_final(const float* __restrict__ sc_w,
                        const float* __restrict__ sc_b,
                        const float* __restrict__ gamma,
                        const float* __restrict__ beta,
                        float* __restrict__ out) {
    __shared__ __align__(16) float ws[8 * 512];   // [ci][j]
    int b = blockIdx.z;
    int co0 = blockIdx.y * 8;
    int p = blockIdx.x * 128 + threadIdx.x;
    for (int i = threadIdx.x; i < 4096; i += 128) {
        int j = i >> 9, ci = i & 511;
        ws[ci * 8 + j] = sc_w[(co0 + j) * 512 + ci];
    }
    __syncthreads();
    ull a[4] = {0ull, 0ull, 0ull, 0ull};
    const float* xp = g_x + b * 512 * HW + p;
#pragma unroll 4
    for (int ci = 0; ci < 512; ci++) {
        float xv = __ldg(xp + ci * HW);
        ull xv2 = pack2(xv, xv);
        const ull* wr = (const ull*)(ws + ci * 8);
        fma2(a[0], wr[0], xv2);
        fma2(a[1], wr[1], xv2);
        fma2(a[2], wr[2], xv2);
        fma2(a[3], wr[3], xv2);
    }
#pragma unroll
    for (int jp = 0; jp < 4; jp++) {
        float2 u = unpack2(a[jp]);
#pragma unroll
        for (int half = 0; half < 2; half++) {
            int co = co0 + 2 * jp + half;
            float accv = half ? u.y : u.x;
            float m = g_stats[co], r = g_stats[CO + co];
            float v = (g_dc[(b * CO + co) * HW + p] - m) * r * gamma[co] +
                      beta[co] + accv + sc_b[co];
            out[(b * CO + co) * HW + p] = fmaxf(v, 0.f);
        }
    }
}

// ---------------------------------------------------------------------------
extern "C" void kernel_launch(void* const* d_in, const int* in_sizes, int n_in,
                              void* d_out, int out_size) {
    const float* x1    = (const float*)d_in[0];
    const float* x2    = (const float*)d_in[1];
    const float* up_w  = (const float*)d_in[2];
    const float* up_b  = (const float*)d_in[3];
    const float* off_w = (const float*)d_in[4];
    const float* off_b = (const float*)d_in[5];
    const float* def_w = (const float*)d_in[6];
    const float* def_b = (const float*)d_in[7];
    const float* bn_g  = (const float*)d_in[8];
    const float* bn_b  = (const float*)d_in[9];
    const float* sc_w  = (const float*)d_in[10];
    const float* sc_b  = (const float*)d_in[11];
    float* out = (float*)d_out;

    k_upconv<<<dim3(HWIN / 128, CO / 8, B_), 128>>>(x1, up_w);
    k_copy<<<(B_ * 256 * (HW / 4) + 255) / 256, 256>>>(x2);
    k_upsample<<<(B_ * CO * HW + 255) / 256, 256>>>(up_b);
    k_wt<<<(K2 * CC * CO + 255) / 256, 256>>>(def_w);
    k_offconv<<<dim3(H_, 4, B_), 64>>>(off_w);
    k_offred<<<(B_ * OFFC * HW + 255) / 256, 256>>>(off_b);
    k_deform<<<dim3(HW / PIX, B_), 128>>>(def_b);
    k_stats<<<CO, 256>>>();
    k_final<<<dim3(HW / 128, CO / 8, B_), 128>>>(sc_w, sc_b, bn_g, bn_b, out);
}